// round 15
// baseline (speedup 1.0000x reference)
#include <cuda_runtime.h>
#include <cuda_bf16.h>

// GivensRotationPerHead: H=64 heads, DIM=128, R=8128 rotations (triu i-major order).
// Round 15:
//   - givens: R11's 1-wide pipelined j-sweep, byte-identical (~26us).
//   - combine: latency-floor attack. R14 proved combine is work-invariant
//     (~17us floor): FLOP tricks dead. New shape: grid=256 (4 CTAs/head,
//     22 M-rows each), block=256, full K=88, smem ~53KB -> 2 CTAs/SM
//     co-resident: half the per-CTA critical path, double the warps.
//     R8-style row-major mapping (coalesced stores, broadcast loads).

#define NHEADS 64
#define DIMN   128
#define NROT   8128
#define TPB    128

#define SPLIT_I   40
#define SPLIT_B   5
#define NB        16
#define R_SPLIT   4300
#define RANGE0    4300
#define RANGE1    3828
#define MAXRANGE  4300
#define MDIM      88        // DIMN - SPLIT_I

__device__ __forceinline__ int rbase(int i) { return i * 127 - (i * (i - 1)) / 2; }
__device__ __forceinline__ int blockbase8(int b) { return 988 * b - 32 * b * (b - 1); }

__device__ __forceinline__ void frot(float& vi, float& vj, float a, float b) {
    float ni = fmaf(a, vj, vi);
    vj = fmaf(b, vi, vj);
    vi = ni;
}

// 8 MB global scratch: halfQ[task][128][128], task = head*2 + half
__device__ float g_halfQ[2 * NHEADS * DIMN * DIMN];

#define OFF_T   MAXRANGE
#define OFF_FI  (2 * MAXRANGE)
#define OFF_FJ  (3 * MAXRANGE)
#define OFF_AB  (4 * MAXRANGE)
#define OFF_RS  (4 * MAXRANGE + 2 * MAXRANGE)
#define SM_FLOATS (OFF_RS + DIMN)     // 25928 floats = 103712 B

__global__ __launch_bounds__(TPB)
void givens_half_kernel(const float* __restrict__ thetas,
                        const int*   __restrict__ rot_i,
                        const int*   __restrict__ rot_j)
{
    extern __shared__ float sm[];
    float*  C  = sm;
    float*  T  = sm + OFF_T;
    float*  Fi = sm + OFF_FI;
    float*  Fj = sm + OFF_FJ;
    float*  Qs = sm;                         // aliases C/T/Fi after pass 3
    float2* AB = (float2*)(sm + OFF_AB);
    float*  rs = sm + OFF_RS;

    const int tid  = threadIdx.x;
    const int task = blockIdx.x;
    const int head = task >> 1;
    const int half = task & 1;

    const int r0    = half ? R_SPLIT : 0;
    const int range = half ? RANGE1 : RANGE0;
    const int b_lo  = half ? SPLIT_B : 0;
    const int b_hi  = half ? NB : SPLIT_B;
    const int ilo   = half ? SPLIT_I : 0;
    const int ihi   = half ? DIMN : SPLIT_I;

    const float* th = thetas + (size_t)head * NROT + r0;

    // ---- pass 1: cos / tan ----
    for (int rl = tid; rl < range; rl += TPB) {
        float s, c;
        __sincosf(th[rl], &s, &c);
        C[rl] = c;
        T[rl] = __fdividef(s, c);
    }
    __syncthreads();

    // ---- pass 2: per-row prefix products (row = tid) ----
    {
        const int m = tid;
        float f = 1.0f;
        int kend = m < ihi ? m : ihi;
        for (int k = ilo; k < kend; ++k) {
            int rl = rbase(k) + (m - k - 1) - r0;
            Fj[rl] = f;
            f *= C[rl];
        }
        if (m >= ilo && m < ihi) {
            int base = rbase(m) - r0;
            for (int j = m + 1; j < DIMN; ++j) {
                int rl = base + (j - m - 1);
                Fi[rl] = f;
                f *= C[rl];
            }
        }
        rs[m] = f;
    }
    __syncthreads();

    // ---- pass 3: alpha/beta into blocked AB table ([j][a], 8 float2 per j) ----
    for (int rl = tid; rl < range; rl += TPB) {
        int r = r0 + rl;
        int i = rot_i[r];
        int j = rot_j[r];
        float t  = T[rl];
        float fi = Fi[rl];
        float fj = Fj[rl];
        float al =  t * __fdividef(fj, fi);
        float be = -t * __fdividef(fi, fj);
        int b  = i >> 3;
        int a  = i & 7;
        int i0 = b << 3;
        int bb = blockbase8(b) - r0;
        int pos;
        if (j < i0 + 8) {
            int jj = j - i0;
            pos = bb + a * 7 - (a * (a - 1)) / 2 + (jj - a - 1);
        } else {
            pos = bb + 28 + ((j - i0 - 8) << 3) + a;
        }
        AB[pos] = make_float2(al, be);
    }
    __syncthreads();

    // ---- init Q~ = I ----
    for (int idx = tid; idx < DIMN * DIMN; idx += TPB)
        Qs[idx] = ((idx >> 7) == (idx & 127)) ? 1.0f : 0.0f;
    __syncthreads();

    // ---- main loop: 8-row register blocks, 1-wide j with software pipeline ----
    // Prefetch-next-before-store is load-bearing (smem alias ordering).
    // half1 columns < 40 are exact identity; warp 0 (cols 0-31) skips entirely.
    if (!(half && tid < 32)) {
        const int t = tid;
        for (int b = b_lo; b < b_hi; ++b) {
            const int i0 = b << 3;
            const int bb = blockbase8(b) - r0;

            float v[8];
            #pragma unroll
            for (int a = 0; a < 8; ++a) v[a] = Qs[(i0 + a) * DIMN + t];

            // intra-block triangle (28 rotations, original order)
            {
                const float2* abt = AB + bb;
                int p = 0;
                #pragma unroll
                for (int a = 0; a < 7; ++a)
                    #pragma unroll
                    for (int jj = a + 1; jj < 8; ++jj) {
                        float2 ab = abt[p++];
                        frot(v[a], v[jj], ab.x, ab.y);
                    }
            }

            // j-sweep with software pipeline (prefetch next vj + AB before store)
            if (i0 + 8 < DIMN) {
                int j = i0 + 8;
                float vj = Qs[j * DIMN + t];
                const float4* ap = (const float4*)(AB + bb + 28);
                float4 a0 = ap[0], a1 = ap[1], a2 = ap[2], a3 = ap[3];

                #pragma unroll 2
                for (; j < DIMN; ++j) {
                    int jn = (j + 1 < DIMN) ? j + 1 : j;            // clamped prefetch
                    const float4* np =
                        (const float4*)(AB + bb + 28 + ((jn - i0 - 8) << 3));
                    float4 n0 = np[0], n1 = np[1], n2 = np[2], n3 = np[3];
                    float  vn = Qs[jn * DIMN + t];

                    frot(v[0], vj, a0.x, a0.y);
                    frot(v[1], vj, a0.z, a0.w);
                    frot(v[2], vj, a1.x, a1.y);
                    frot(v[3], vj, a1.z, a1.w);
                    frot(v[4], vj, a2.x, a2.y);
                    frot(v[5], vj, a2.z, a2.w);
                    frot(v[6], vj, a3.x, a3.y);
                    frot(v[7], vj, a3.z, a3.w);

                    Qs[j * DIMN + t] = vj;
                    vj = vn;
                    a0 = n0; a1 = n1; a2 = n2; a3 = n3;
                }
            }

            #pragma unroll
            for (int a = 0; a < 8; ++a) Qs[(i0 + a) * DIMN + t] = v[a];
        }
    }
    __syncthreads();

    // ---- write scaled half to global scratch ----
    float* o = g_halfQ + (size_t)task * DIMN * DIMN;
    for (int idx = tid; idx < DIMN * DIMN; idx += TPB)
        o[idx] = rs[idx >> 7] * Qs[idx];
}

// ============================================================================
// Structural combine v4 (latency-floor attack):
//   out[0:40, :] = H0[0:40, :]                   (copy, q=0 CTA)
//   out[40+mq+m][:] = sum_k M[mq+m][k] * H0[40+k][:]   (full K=88)
// grid = 4*NHEADS (4 CTAs/head, mq = q*22), block = 256, smem ~53KB ->
// 2 CTAs/SM co-resident. Thread tile 2 rows x 8 cols (11x16 grid, 176 active).
// Row-major warps: coalesced stores, broadcast a-loads, conflict-free b-loads.
// ============================================================================
#define GTPB 256
#define CSM_B  0                          // sB [88][128]
#define CSM_M  (MDIM * DIMN)              // sM [22][88]
#define CSM_FLOATS (MDIM * DIMN + 22 * MDIM)   // 13200 floats = 52800 B

__global__ __launch_bounds__(GTPB)
void combine_kernel(float* __restrict__ out)
{
    extern __shared__ float gs[];
    float* sB = gs + CSM_B;      // H0 rows 40..127: [k][c]
    float* sM = gs + CSM_M;      // M rows [mq, mq+22): [m][k]

    const int tid  = threadIdx.x;
    const int head = blockIdx.x >> 2;
    const int q    = blockIdx.x & 3;
    const int mq   = q * 22;

    const float* A = g_halfQ + (size_t)(head * 2 + 0) * DIMN * DIMN;  // H0
    const float* B = g_halfQ + (size_t)(head * 2 + 1) * DIMN * DIMN;  // H1
    float*       O = out + (size_t)head * DIMN * DIMN;

    // sB: H0[40:128][:] = 2816 float4
    {
        const float4* src = (const float4*)(A + 40 * DIMN);
        for (int i = tid; i < MDIM * DIMN / 4; i += GTPB)
            ((float4*)sB)[i] = src[i];
    }
    // sM: M[mq+m][k] = H1[40+mq+m][40+k], 22 float4 per row, 22 rows
    for (int i = tid; i < 22 * 22; i += GTPB) {
        int m = i / 22, k4 = i % 22;
        ((float4*)(sM + m * MDIM))[k4] =
            *(const float4*)(B + (size_t)(40 + mq + m) * DIMN + 40 + k4 * 4);
    }
    // q=0 CTA copies out rows 0..39 (exact)
    if (q == 0) {
        const float4* src = (const float4*)A;
        float4* dst = (float4*)O;
        for (int i = tid; i < 40 * DIMN / 4; i += GTPB)
            dst[i] = src[i];
    }
    __syncthreads();

    // GEMM: 22 rows x 128 cols, K=88. Thread grid 11x16, tile 2 rows x 8 cols.
    const int tx = tid & 15;        // col group -> c0 = tx*8
    const int ty = tid >> 4;        // row group 0..15, active < 11
    const int c0 = tx << 3;
    const int r0 = ty * 2;

    if (ty < 11) {
        float acc[2][8];
        #pragma unroll
        for (int i = 0; i < 2; ++i)
            #pragma unroll
            for (int j = 0; j < 8; ++j) acc[i][j] = 0.0f;

        const float* m0p = sM + (size_t)r0 * MDIM;
        const float* m1p = m0p + MDIM;

        float a0 = m0p[0];
        float a1 = m1p[0];
        float4 b0 = *(const float4*)&sB[c0];
        float4 b1 = *(const float4*)&sB[c0 + 4];

        #pragma unroll 2
        for (int k = 0; k < MDIM; ++k) {
            int kn = (k + 1 < MDIM) ? k + 1 : k;
            float na0 = m0p[kn];
            float na1 = m1p[kn];
            float4 nb0 = *(const float4*)&sB[kn * DIMN + c0];
            float4 nb1 = *(const float4*)&sB[kn * DIMN + c0 + 4];

            acc[0][0] = fmaf(a0, b0.x, acc[0][0]);
            acc[0][1] = fmaf(a0, b0.y, acc[0][1]);
            acc[0][2] = fmaf(a0, b0.z, acc[0][2]);
            acc[0][3] = fmaf(a0, b0.w, acc[0][3]);
            acc[0][4] = fmaf(a0, b1.x, acc[0][4]);
            acc[0][5] = fmaf(a0, b1.y, acc[0][5]);
            acc[0][6] = fmaf(a0, b1.z, acc[0][6]);
            acc[0][7] = fmaf(a0, b1.w, acc[0][7]);

            acc[1][0] = fmaf(a1, b0.x, acc[1][0]);
            acc[1][1] = fmaf(a1, b0.y, acc[1][1]);
            acc[1][2] = fmaf(a1, b0.z, acc[1][2]);
            acc[1][3] = fmaf(a1, b0.w, acc[1][3]);
            acc[1][4] = fmaf(a1, b1.x, acc[1][4]);
            acc[1][5] = fmaf(a1, b1.y, acc[1][5]);
            acc[1][6] = fmaf(a1, b1.z, acc[1][6]);
            acc[1][7] = fmaf(a1, b1.w, acc[1][7]);

            a0 = na0; a1 = na1;
            b0 = nb0; b1 = nb1;
        }

        const int rowbase = 40 + mq + r0;
        #pragma unroll
        for (int i = 0; i < 2; ++i) {
            float* o = O + (size_t)(rowbase + i) * DIMN + c0;
            *(float4*)o       = make_float4(acc[i][0], acc[i][1], acc[i][2], acc[i][3]);
            *(float4*)(o + 4) = make_float4(acc[i][4], acc[i][5], acc[i][6], acc[i][7]);
        }
    }
}

extern "C" void kernel_launch(void* const* d_in, const int* in_sizes, int n_in,
                              void* d_out, int out_size)
{
    const float* thetas = (const float*)d_in[0];
    const int*   ri     = (const int*)d_in[1];
    const int*   rj     = (const int*)d_in[2];
    float*       out    = (float*)d_out;

    const size_t smem1 = SM_FLOATS * sizeof(float);    // 103712 B
    const size_t smem2 = CSM_FLOATS * sizeof(float);   //  52800 B
    cudaFuncSetAttribute(givens_half_kernel,
                         cudaFuncAttributeMaxDynamicSharedMemorySize, (int)smem1);
    cudaFuncSetAttribute(combine_kernel,
                         cudaFuncAttributeMaxDynamicSharedMemorySize, (int)smem2);

    givens_half_kernel<<<2 * NHEADS, TPB, smem1>>>(thetas, ri, rj);
    combine_kernel<<<4 * NHEADS, GTPB, smem2>>>(out);
}

// round 16
// speedup vs baseline: 1.0876x; 1.0876x over previous
#include <cuda_runtime.h>
#include <cuda_bf16.h>

// GivensRotationPerHead: H=64 heads, DIM=128, R=8128 rotations (triu i-major order).
// Round 16:
//   - givens: 16-row register blocks, SPLIT_I=32. Halves the j-step makespan
//     (520 -> 240) while per-j cost grows sublinearly. R6's load-before-store
//     pipeline ordering preserved (load-bearing). Reorder legality = same
//     disjoint-commute argument as 8-row blocks.
//   - combine: R8 structure (proven 17.5us floor) adapted to SPLIT=32:
//     copy rows 0-31; out[32:,:] = M(96x96) @ H0[32:,:], 2 CTAs/head x 48 rows,
//     K=96 split 2x48, 512 threads.

#define NHEADS 64
#define DIMN   128
#define NROT   8128
#define TPB    128

#define SPLIT_I   32         // 16-row block boundary
#define NB16      8
#define SPLIT_B   2          // half0: blocks 0-1, half1: blocks 2-7
#define R_SPLIT   3568       // rbase(32)
#define RANGE0    3568
#define RANGE1    4560
#define MAXRANGE  4560
#define MDIM      96         // DIMN - SPLIT_I

__device__ __forceinline__ int rbase(int i) { return i * 127 - (i * (i - 1)) / 2; }
// base of 16-row block b: block size = 1912 - 256b (120 triangle + sweep*16)
__device__ __forceinline__ int blockbase16(int b) { return 1912 * b - 128 * b * (b - 1); }

__device__ __forceinline__ void frot(float& vi, float& vj, float a, float b) {
    float ni = fmaf(a, vj, vi);
    vj = fmaf(b, vi, vj);
    vi = ni;
}

// 8 MB global scratch: halfQ[task][128][128], task = head*2 + half
__device__ float g_halfQ[2 * NHEADS * DIMN * DIMN];

#define OFF_T   MAXRANGE
#define OFF_FI  (2 * MAXRANGE)
#define OFF_FJ  (3 * MAXRANGE)
#define OFF_AB  (4 * MAXRANGE)
#define OFF_RS  (6 * MAXRANGE)
#define SM_FLOATS (OFF_RS + DIMN)     // 27488 floats = 109952 B

__global__ __launch_bounds__(TPB)
void givens_half_kernel(const float* __restrict__ thetas,
                        const int*   __restrict__ rot_i,
                        const int*   __restrict__ rot_j)
{
    extern __shared__ float sm[];
    float*  C  = sm;
    float*  T  = sm + OFF_T;
    float*  Fi = sm + OFF_FI;
    float*  Fj = sm + OFF_FJ;
    float*  Qs = sm;                         // aliases C/T/Fi/Fj after pass 3
    float2* AB = (float2*)(sm + OFF_AB);
    float*  rs = sm + OFF_RS;

    const int tid  = threadIdx.x;
    const int task = blockIdx.x;
    const int head = task >> 1;
    const int half = task & 1;

    const int r0    = half ? R_SPLIT : 0;
    const int range = half ? RANGE1 : RANGE0;
    const int b_lo  = half ? SPLIT_B : 0;
    const int b_hi  = half ? NB16 : SPLIT_B;
    const int ilo   = half ? SPLIT_I : 0;
    const int ihi   = half ? DIMN : SPLIT_I;

    const float* th = thetas + (size_t)head * NROT + r0;

    // ---- pass 1: cos / tan ----
    for (int rl = tid; rl < range; rl += TPB) {
        float s, c;
        __sincosf(th[rl], &s, &c);
        C[rl] = c;
        T[rl] = __fdividef(s, c);
    }
    __syncthreads();

    // ---- pass 2: per-row prefix products (row = tid), original i-major order ----
    {
        const int m = tid;
        float f = 1.0f;
        int kend = m < ihi ? m : ihi;
        for (int k = ilo; k < kend; ++k) {          // j-role: rotation (k, m)
            int rl = rbase(k) + (m - k - 1) - r0;
            Fj[rl] = f;
            f *= C[rl];
        }
        if (m >= ilo && m < ihi) {                  // i-role: rotations (m, j)
            int base = rbase(m) - r0;
            for (int j = m + 1; j < DIMN; ++j) {
                int rl = base + (j - m - 1);
                Fi[rl] = f;
                f *= C[rl];
            }
        }
        rs[m] = f;
    }
    __syncthreads();

    // ---- pass 3: alpha/beta into blocked AB table (16-row blocks) ----
    // triangle: (a, jj) -> a*15 - a(a-1)/2 + (jj-a-1); sweep: [j][a] 16 f2/j
    for (int rl = tid; rl < range; rl += TPB) {
        int r = r0 + rl;
        int i = rot_i[r];
        int j = rot_j[r];
        float t  = T[rl];
        float fi = Fi[rl];
        float fj = Fj[rl];
        float al =  t * __fdividef(fj, fi);
        float be = -t * __fdividef(fi, fj);
        int b  = i >> 4;
        int a  = i & 15;
        int i0 = b << 4;
        int bb = blockbase16(b) - r0;
        int pos;
        if (j < i0 + 16) {
            int jj = j - i0;
            pos = bb + a * 15 - (a * (a - 1)) / 2 + (jj - a - 1);
        } else {
            pos = bb + 120 + ((j - i0 - 16) << 4) + a;
        }
        AB[pos] = make_float2(al, be);
    }
    __syncthreads();

    // ---- init Q~ = I ----
    for (int idx = tid; idx < DIMN * DIMN; idx += TPB)
        Qs[idx] = ((idx >> 7) == (idx & 127)) ? 1.0f : 0.0f;
    __syncthreads();

    // ---- main loop: 16-row register blocks, 1-wide pipelined j-sweep ----
    // Loads BEFORE the store each iteration (load-bearing: ptxas cannot hoist
    // smem loads over may-alias smem stores).
    // half1 columns < 32 are exact identity; warp 0 skips entirely.
    if (!(half && tid < 32)) {
        const int t = tid;
        for (int b = b_lo; b < b_hi; ++b) {
            const int i0 = b << 4;
            const int bb = blockbase16(b) - r0;

            float v[16];
            #pragma unroll
            for (int a = 0; a < 16; ++a) v[a] = Qs[(i0 + a) * DIMN + t];

            // intra-block triangle (120 rotations, original a-major order)
            {
                const float2* abt = AB + bb;
                int p = 0;
                #pragma unroll
                for (int a = 0; a < 15; ++a)
                    #pragma unroll
                    for (int jj = a + 1; jj < 16; ++jj) {
                        float2 ab = abt[p++];
                        frot(v[a], v[jj], ab.x, ab.y);
                    }
            }

            // j-sweep with software pipeline (prefetch next vj + AB before store)
            if (i0 + 16 < DIMN) {
                int j = i0 + 16;
                float vj = Qs[j * DIMN + t];
                const float4* ap = (const float4*)(AB + bb + 120);
                float4 c0 = ap[0], c1 = ap[1], c2 = ap[2], c3 = ap[3];
                float4 c4 = ap[4], c5 = ap[5], c6 = ap[6], c7 = ap[7];

                for (; j < DIMN; ++j) {
                    int jn = (j + 1 < DIMN) ? j + 1 : j;   // clamped prefetch
                    const float4* np =
                        (const float4*)(AB + bb + 120 + ((jn - i0 - 16) << 4));
                    float4 n0 = np[0], n1 = np[1], n2 = np[2], n3 = np[3];
                    float4 n4 = np[4], n5 = np[5], n6 = np[6], n7 = np[7];
                    float  vn = Qs[jn * DIMN + t];

                    frot(v[0],  vj, c0.x, c0.y);
                    frot(v[1],  vj, c0.z, c0.w);
                    frot(v[2],  vj, c1.x, c1.y);
                    frot(v[3],  vj, c1.z, c1.w);
                    frot(v[4],  vj, c2.x, c2.y);
                    frot(v[5],  vj, c2.z, c2.w);
                    frot(v[6],  vj, c3.x, c3.y);
                    frot(v[7],  vj, c3.z, c3.w);
                    frot(v[8],  vj, c4.x, c4.y);
                    frot(v[9],  vj, c4.z, c4.w);
                    frot(v[10], vj, c5.x, c5.y);
                    frot(v[11], vj, c5.z, c5.w);
                    frot(v[12], vj, c6.x, c6.y);
                    frot(v[13], vj, c6.z, c6.w);
                    frot(v[14], vj, c7.x, c7.y);
                    frot(v[15], vj, c7.z, c7.w);

                    Qs[j * DIMN + t] = vj;
                    vj = vn;
                    c0 = n0; c1 = n1; c2 = n2; c3 = n3;
                    c4 = n4; c5 = n5; c6 = n6; c7 = n7;
                }
            }

            #pragma unroll
            for (int a = 0; a < 16; ++a) Qs[(i0 + a) * DIMN + t] = v[a];
        }
    }
    __syncthreads();

    // ---- write scaled half to global scratch ----
    float* o = g_halfQ + (size_t)task * DIMN * DIMN;
    for (int idx = tid; idx < DIMN * DIMN; idx += TPB)
        o[idx] = rs[idx >> 7] * Qs[idx];
}

// ============================================================================
// Structural combine (R8 structure, SPLIT=32):
//   out[0:32, :] = H0[0:32, :]                        (copy, rh=0 CTA)
//   out[32+mb : 32+mb+48, :] = M[mb:mb+48, :] @ H0[32:, :]   (mb = rh*48)
// 512 threads: two 256-thread groups each do half of K (48), partials reduced
// through smem. Per-thread tile 3x8 over exactly 48 GEMM rows.
// ============================================================================
#define GTPB 512
#define GSM_B  0                                   // sB [96][128]
#define GSM_M  (MDIM * DIMN)                       // sM [48][96]
#define GSM_P  (MDIM * DIMN + 48 * MDIM)           // sP [48][128]
#define GSM_FLOATS (MDIM * DIMN + 48 * MDIM + 48 * DIMN)   // 23040 fl = 92160 B

__global__ __launch_bounds__(GTPB)
void combine_kernel(float* __restrict__ out)
{
    extern __shared__ float gs[];
    float* sB = gs + GSM_B;      // H0 rows 32..127: [k][c]
    float* sM = gs + GSM_M;      // M slice: [m][k]
    float* sP = gs + GSM_P;      // partials from K-group 1

    const int tid  = threadIdx.x;
    const int head = blockIdx.x >> 1;
    const int rh   = blockIdx.x & 1;
    const int mb   = rh * 48;

    const float* A = g_halfQ + (size_t)(head * 2 + 0) * DIMN * DIMN;  // H0
    const float* B = g_halfQ + (size_t)(head * 2 + 1) * DIMN * DIMN;  // H1
    float*       O = out + (size_t)head * DIMN * DIMN;

    // sB: H0[32:128][:] = 3072 float4
    {
        const float4* src = (const float4*)(A + SPLIT_I * DIMN);
        for (int i = tid; i < MDIM * DIMN / 4; i += GTPB)
            ((float4*)sB)[i] = src[i];
    }
    // sM: M[mb+m][k] = H1[32+mb+m][32+k], 24 float4 per row, 48 rows
    for (int i = tid; i < 48 * 24; i += GTPB) {
        int m = i / 24, k4 = i % 24;
        ((float4*)(sM + m * MDIM))[k4] =
            *(const float4*)(B + (size_t)(SPLIT_I + mb + m) * DIMN + SPLIT_I + k4 * 4);
    }
    // rh=0 CTA copies out rows 0..31 (exact)
    if (rh == 0) {
        const float4* src = (const float4*)A;
        float4* dst = (float4*)O;
        for (int i = tid; i < SPLIT_I * DIMN / 4; i += GTPB)
            dst[i] = src[i];
    }
    __syncthreads();

    // GEMM: 48 rows x 128 cols, K=96 split as 2x48 across thread groups.
    const int g    = tid >> 8;          // K-group 0/1
    const int tid2 = tid & 255;
    const int tx   = tid2 & 15;
    const int ty   = tid2 >> 4;
    const int c0   = tx << 3;
    const int m0   = ty * 3;            // rows 0..47 exactly
    const int kb   = g * 48;

    float acc[3][8];
    #pragma unroll
    for (int i = 0; i < 3; ++i)
        #pragma unroll
        for (int j = 0; j < 8; ++j) acc[i][j] = 0.0f;

    float a0 = sM[(m0 + 0) * MDIM + kb];
    float a1 = sM[(m0 + 1) * MDIM + kb];
    float a2 = sM[(m0 + 2) * MDIM + kb];
    float4 b0 = *(const float4*)&sB[kb * DIMN + c0];
    float4 b1 = *(const float4*)&sB[kb * DIMN + c0 + 4];

    #pragma unroll 2
    for (int kk = 0; kk < 48; ++kk) {
        int k  = kb + kk;
        int kn = (kk + 1 < 48) ? k + 1 : k;
        float na0 = sM[(m0 + 0) * MDIM + kn];
        float na1 = sM[(m0 + 1) * MDIM + kn];
        float na2 = sM[(m0 + 2) * MDIM + kn];
        float4 nb0 = *(const float4*)&sB[kn * DIMN + c0];
        float4 nb1 = *(const float4*)&sB[kn * DIMN + c0 + 4];

        acc[0][0] = fmaf(a0, b0.x, acc[0][0]);
        acc[0][1] = fmaf(a0, b0.y, acc[0][1]);
        acc[0][2] = fmaf(a0, b0.z, acc[0][2]);
        acc[0][3] = fmaf(a0, b0.w, acc[0][3]);
        acc[0][4] = fmaf(a0, b1.x, acc[0][4]);
        acc[0][5] = fmaf(a0, b1.y, acc[0][5]);
        acc[0][6] = fmaf(a0, b1.z, acc[0][6]);
        acc[0][7] = fmaf(a0, b1.w, acc[0][7]);

        acc[1][0] = fmaf(a1, b0.x, acc[1][0]);
        acc[1][1] = fmaf(a1, b0.y, acc[1][1]);
        acc[1][2] = fmaf(a1, b0.z, acc[1][2]);
        acc[1][3] = fmaf(a1, b0.w, acc[1][3]);
        acc[1][4] = fmaf(a1, b1.x, acc[1][4]);
        acc[1][5] = fmaf(a1, b1.y, acc[1][5]);
        acc[1][6] = fmaf(a1, b1.z, acc[1][6]);
        acc[1][7] = fmaf(a1, b1.w, acc[1][7]);

        acc[2][0] = fmaf(a2, b0.x, acc[2][0]);
        acc[2][1] = fmaf(a2, b0.y, acc[2][1]);
        acc[2][2] = fmaf(a2, b0.z, acc[2][2]);
        acc[2][3] = fmaf(a2, b0.w, acc[2][3]);
        acc[2][4] = fmaf(a2, b1.x, acc[2][4]);
        acc[2][5] = fmaf(a2, b1.y, acc[2][5]);
        acc[2][6] = fmaf(a2, b1.z, acc[2][6]);
        acc[2][7] = fmaf(a2, b1.w, acc[2][7]);

        a0 = na0; a1 = na1; a2 = na2;
        b0 = nb0; b1 = nb1;
    }

    // K-group 1 stores partials; group 0 adds and writes out.
    if (g == 1) {
        #pragma unroll
        for (int i = 0; i < 3; ++i) {
            int m = m0 + i;
            float* p = sP + m * DIMN + c0;
            *(float4*)p       = make_float4(acc[i][0], acc[i][1], acc[i][2], acc[i][3]);
            *(float4*)(p + 4) = make_float4(acc[i][4], acc[i][5], acc[i][6], acc[i][7]);
        }
    }
    __syncthreads();
    if (g == 0) {
        const int rowbase = SPLIT_I + mb;
        #pragma unroll
        for (int i = 0; i < 3; ++i) {
            int m = m0 + i;
            const float* p = sP + m * DIMN + c0;
            float4 p0 = *(const float4*)p;
            float4 p1 = *(const float4*)(p + 4);
            float* o = O + (size_t)(rowbase + m) * DIMN + c0;
            *(float4*)o = make_float4(acc[i][0] + p0.x, acc[i][1] + p0.y,
                                      acc[i][2] + p0.z, acc[i][3] + p0.w);
            *(float4*)(o + 4) = make_float4(acc[i][4] + p1.x, acc[i][5] + p1.y,
                                            acc[i][6] + p1.z, acc[i][7] + p1.w);
        }
    }
}

extern "C" void kernel_launch(void* const* d_in, const int* in_sizes, int n_in,
                              void* d_out, int out_size)
{
    const float* thetas = (const float*)d_in[0];
    const int*   ri     = (const int*)d_in[1];
    const int*   rj     = (const int*)d_in[2];
    float*       out    = (float*)d_out;

    const size_t smem1 = SM_FLOATS * sizeof(float);    // 109952 B
    const size_t smem2 = GSM_FLOATS * sizeof(float);   //  92160 B
    cudaFuncSetAttribute(givens_half_kernel,
                         cudaFuncAttributeMaxDynamicSharedMemorySize, (int)smem1);
    cudaFuncSetAttribute(combine_kernel,
                         cudaFuncAttributeMaxDynamicSharedMemorySize, (int)smem2);

    givens_half_kernel<<<2 * NHEADS, TPB, smem1>>>(thetas, ri, rj);
    combine_kernel<<<2 * NHEADS, GTPB, smem2>>>(out);
}

// round 17
// speedup vs baseline: 1.0906x; 1.0027x over previous
#include <cuda_runtime.h>
#include <cuda_bf16.h>

// GivensRotationPerHead: H=64 heads, DIM=128, R=8128 rotations (triu i-major order).
// Round 17:
//   - givens: R11/R14 1-wide pipelined j-sweep, SPLIT 40, byte-identical (~26us;
//     8-row vs 16-row proved equivalent -> parked at proven version).
//   - combine: warp-scaling attack. Time tracks warps/SMSP (128t:27us,
//     256t:21us, 512t:17.5us, issue only 25%): go to 1024 threads, K=88
//     split 4x22, 3 smem partial buffers, single sB load per CTA.

#define NHEADS 64
#define DIMN   128
#define NROT   8128
#define TPB    128

#define SPLIT_I   40
#define SPLIT_B   5
#define NB        16
#define R_SPLIT   4300
#define RANGE0    4300
#define RANGE1    3828
#define MAXRANGE  4300
#define MDIM      88        // DIMN - SPLIT_I

__device__ __forceinline__ int rbase(int i) { return i * 127 - (i * (i - 1)) / 2; }
__device__ __forceinline__ int blockbase8(int b) { return 988 * b - 32 * b * (b - 1); }

__device__ __forceinline__ void frot(float& vi, float& vj, float a, float b) {
    float ni = fmaf(a, vj, vi);
    vj = fmaf(b, vi, vj);
    vi = ni;
}

// 8 MB global scratch: halfQ[task][128][128], task = head*2 + half
__device__ float g_halfQ[2 * NHEADS * DIMN * DIMN];

#define OFF_T   MAXRANGE
#define OFF_FI  (2 * MAXRANGE)
#define OFF_FJ  (3 * MAXRANGE)
#define OFF_AB  (4 * MAXRANGE)
#define OFF_RS  (4 * MAXRANGE + 2 * MAXRANGE)
#define SM_FLOATS (OFF_RS + DIMN)     // 25928 floats = 103712 B

__global__ __launch_bounds__(TPB)
void givens_half_kernel(const float* __restrict__ thetas,
                        const int*   __restrict__ rot_i,
                        const int*   __restrict__ rot_j)
{
    extern __shared__ float sm[];
    float*  C  = sm;
    float*  T  = sm + OFF_T;
    float*  Fi = sm + OFF_FI;
    float*  Fj = sm + OFF_FJ;
    float*  Qs = sm;                         // aliases C/T/Fi after pass 3
    float2* AB = (float2*)(sm + OFF_AB);
    float*  rs = sm + OFF_RS;

    const int tid  = threadIdx.x;
    const int task = blockIdx.x;
    const int head = task >> 1;
    const int half = task & 1;

    const int r0    = half ? R_SPLIT : 0;
    const int range = half ? RANGE1 : RANGE0;
    const int b_lo  = half ? SPLIT_B : 0;
    const int b_hi  = half ? NB : SPLIT_B;
    const int ilo   = half ? SPLIT_I : 0;
    const int ihi   = half ? DIMN : SPLIT_I;

    const float* th = thetas + (size_t)head * NROT + r0;

    // ---- pass 1: cos / tan ----
    for (int rl = tid; rl < range; rl += TPB) {
        float s, c;
        __sincosf(th[rl], &s, &c);
        C[rl] = c;
        T[rl] = __fdividef(s, c);
    }
    __syncthreads();

    // ---- pass 2: per-row prefix products (row = tid) ----
    {
        const int m = tid;
        float f = 1.0f;
        int kend = m < ihi ? m : ihi;
        for (int k = ilo; k < kend; ++k) {
            int rl = rbase(k) + (m - k - 1) - r0;
            Fj[rl] = f;
            f *= C[rl];
        }
        if (m >= ilo && m < ihi) {
            int base = rbase(m) - r0;
            for (int j = m + 1; j < DIMN; ++j) {
                int rl = base + (j - m - 1);
                Fi[rl] = f;
                f *= C[rl];
            }
        }
        rs[m] = f;
    }
    __syncthreads();

    // ---- pass 3: alpha/beta into blocked AB table ([j][a], 8 float2 per j) ----
    for (int rl = tid; rl < range; rl += TPB) {
        int r = r0 + rl;
        int i = rot_i[r];
        int j = rot_j[r];
        float t  = T[rl];
        float fi = Fi[rl];
        float fj = Fj[rl];
        float al =  t * __fdividef(fj, fi);
        float be = -t * __fdividef(fi, fj);
        int b  = i >> 3;
        int a  = i & 7;
        int i0 = b << 3;
        int bb = blockbase8(b) - r0;
        int pos;
        if (j < i0 + 8) {
            int jj = j - i0;
            pos = bb + a * 7 - (a * (a - 1)) / 2 + (jj - a - 1);
        } else {
            pos = bb + 28 + ((j - i0 - 8) << 3) + a;
        }
        AB[pos] = make_float2(al, be);
    }
    __syncthreads();

    // ---- init Q~ = I ----
    for (int idx = tid; idx < DIMN * DIMN; idx += TPB)
        Qs[idx] = ((idx >> 7) == (idx & 127)) ? 1.0f : 0.0f;
    __syncthreads();

    // ---- main loop: 8-row register blocks, 1-wide j with software pipeline ----
    // Prefetch-next-before-store is load-bearing (smem alias ordering).
    // half1 columns < 40 are exact identity; warp 0 (cols 0-31) skips entirely.
    if (!(half && tid < 32)) {
        const int t = tid;
        for (int b = b_lo; b < b_hi; ++b) {
            const int i0 = b << 3;
            const int bb = blockbase8(b) - r0;

            float v[8];
            #pragma unroll
            for (int a = 0; a < 8; ++a) v[a] = Qs[(i0 + a) * DIMN + t];

            // intra-block triangle (28 rotations, original order)
            {
                const float2* abt = AB + bb;
                int p = 0;
                #pragma unroll
                for (int a = 0; a < 7; ++a)
                    #pragma unroll
                    for (int jj = a + 1; jj < 8; ++jj) {
                        float2 ab = abt[p++];
                        frot(v[a], v[jj], ab.x, ab.y);
                    }
            }

            // j-sweep with software pipeline (prefetch next vj + AB before store)
            if (i0 + 8 < DIMN) {
                int j = i0 + 8;
                float vj = Qs[j * DIMN + t];
                const float4* ap = (const float4*)(AB + bb + 28);
                float4 a0 = ap[0], a1 = ap[1], a2 = ap[2], a3 = ap[3];

                #pragma unroll 2
                for (; j < DIMN; ++j) {
                    int jn = (j + 1 < DIMN) ? j + 1 : j;            // clamped prefetch
                    const float4* np =
                        (const float4*)(AB + bb + 28 + ((jn - i0 - 8) << 3));
                    float4 n0 = np[0], n1 = np[1], n2 = np[2], n3 = np[3];
                    float  vn = Qs[jn * DIMN + t];

                    frot(v[0], vj, a0.x, a0.y);
                    frot(v[1], vj, a0.z, a0.w);
                    frot(v[2], vj, a1.x, a1.y);
                    frot(v[3], vj, a1.z, a1.w);
                    frot(v[4], vj, a2.x, a2.y);
                    frot(v[5], vj, a2.z, a2.w);
                    frot(v[6], vj, a3.x, a3.y);
                    frot(v[7], vj, a3.z, a3.w);

                    Qs[j * DIMN + t] = vj;
                    vj = vn;
                    a0 = n0; a1 = n1; a2 = n2; a3 = n3;
                }
            }

            #pragma unroll
            for (int a = 0; a < 8; ++a) Qs[(i0 + a) * DIMN + t] = v[a];
        }
    }
    __syncthreads();

    // ---- write scaled half to global scratch ----
    float* o = g_halfQ + (size_t)task * DIMN * DIMN;
    for (int idx = tid; idx < DIMN * DIMN; idx += TPB)
        o[idx] = rs[idx >> 7] * Qs[idx];
}

// ============================================================================
// Structural combine v5 (warp scaling):
//   out[0:40, :] = H0[0:40, :]                        (copy, rh=0 CTA)
//   out[40+mb : 40+mb+44, :] = M[mb:mb+44, :] @ H0[40:, :]   (mb = rh*44)
// 1024 threads: four 256-thread K-groups (22 k each). Groups 1-3 store
// partials to sP[0..2]; group 0 sums and writes. Per-thread tile 3x8 over
// 44 GEMM rows (sM padded to 48). sB loaded once per CTA (no duplication).
// ============================================================================
#define GTPB 1024
#define PSZ    (44 * DIMN)                          // one partial buffer
#define GSM_B  0                                    // sB [88][128]
#define GSM_M  (MDIM * DIMN)                        // sM [48][88]
#define GSM_P  (MDIM * DIMN + 48 * MDIM)            // sP [3][44][128]
#define GSM_FLOATS (MDIM * DIMN + 48 * MDIM + 3 * PSZ)  // 32384 fl = 129536 B

__global__ __launch_bounds__(GTPB)
void combine_kernel(float* __restrict__ out)
{
    extern __shared__ float gs[];
    float* sB = gs + GSM_B;      // H0 rows 40..127: [k][c]
    float* sM = gs + GSM_M;      // M slice: [m][k], rows 44..47 zero
    float* sP = gs + GSM_P;      // partials from K-groups 1..3

    const int tid  = threadIdx.x;
    const int head = blockIdx.x >> 1;
    const int rh   = blockIdx.x & 1;
    const int mb   = rh * 44;

    const float* A = g_halfQ + (size_t)(head * 2 + 0) * DIMN * DIMN;  // H0
    const float* B = g_halfQ + (size_t)(head * 2 + 1) * DIMN * DIMN;  // H1
    float*       O = out + (size_t)head * DIMN * DIMN;

    {
        const float4* src = (const float4*)(A + 40 * DIMN);
        for (int i = tid; i < MDIM * DIMN / 4; i += GTPB)
            ((float4*)sB)[i] = src[i];
    }
    for (int i = tid; i < 4 * MDIM; i += GTPB)
        sM[44 * MDIM + i] = 0.0f;
    for (int i = tid; i < 44 * 22; i += GTPB) {
        int m = i / 22, k4 = i % 22;
        ((float4*)(sM + m * MDIM))[k4] =
            *(const float4*)(B + (size_t)(40 + mb + m) * DIMN + 40 + k4 * 4);
    }
    if (rh == 0) {
        const float4* src = (const float4*)A;
        float4* dst = (float4*)O;
        for (int i = tid; i < 40 * DIMN / 4; i += GTPB)
            dst[i] = src[i];
    }
    __syncthreads();

    // GEMM: 44 rows x 128 cols, K=88 split as 4x22 across thread groups.
    const int g    = tid >> 8;          // K-group 0..3
    const int tid2 = tid & 255;
    const int tx   = tid2 & 15;
    const int ty   = tid2 >> 4;
    const int c0   = tx << 3;
    const int m0   = ty * 3;
    const int kb   = g * 22;

    float acc[3][8];
    #pragma unroll
    for (int i = 0; i < 3; ++i)
        #pragma unroll
        for (int j = 0; j < 8; ++j) acc[i][j] = 0.0f;

    float a0 = sM[(m0 + 0) * MDIM + kb];
    float a1 = sM[(m0 + 1) * MDIM + kb];
    float a2 = sM[(m0 + 2) * MDIM + kb];
    float4 b0 = *(const float4*)&sB[kb * DIMN + c0];
    float4 b1 = *(const float4*)&sB[kb * DIMN + c0 + 4];

    #pragma unroll 2
    for (int kk = 0; kk < 22; ++kk) {
        int k  = kb + kk;
        int kn = (kk + 1 < 22) ? k + 1 : k;
        float na0 = sM[(m0 + 0) * MDIM + kn];
        float na1 = sM[(m0 + 1) * MDIM + kn];
        float na2 = sM[(m0 + 2) * MDIM + kn];
        float4 nb0 = *(const float4*)&sB[kn * DIMN + c0];
        float4 nb1 = *(const float4*)&sB[kn * DIMN + c0 + 4];

        acc[0][0] = fmaf(a0, b0.x, acc[0][0]);
        acc[0][1] = fmaf(a0, b0.y, acc[0][1]);
        acc[0][2] = fmaf(a0, b0.z, acc[0][2]);
        acc[0][3] = fmaf(a0, b0.w, acc[0][3]);
        acc[0][4] = fmaf(a0, b1.x, acc[0][4]);
        acc[0][5] = fmaf(a0, b1.y, acc[0][5]);
        acc[0][6] = fmaf(a0, b1.z, acc[0][6]);
        acc[0][7] = fmaf(a0, b1.w, acc[0][7]);

        acc[1][0] = fmaf(a1, b0.x, acc[1][0]);
        acc[1][1] = fmaf(a1, b0.y, acc[1][1]);
        acc[1][2] = fmaf(a1, b0.z, acc[1][2]);
        acc[1][3] = fmaf(a1, b0.w, acc[1][3]);
        acc[1][4] = fmaf(a1, b1.x, acc[1][4]);
        acc[1][5] = fmaf(a1, b1.y, acc[1][5]);
        acc[1][6] = fmaf(a1, b1.z, acc[1][6]);
        acc[1][7] = fmaf(a1, b1.w, acc[1][7]);

        acc[2][0] = fmaf(a2, b0.x, acc[2][0]);
        acc[2][1] = fmaf(a2, b0.y, acc[2][1]);
        acc[2][2] = fmaf(a2, b0.z, acc[2][2]);
        acc[2][3] = fmaf(a2, b0.w, acc[2][3]);
        acc[2][4] = fmaf(a2, b1.x, acc[2][4]);
        acc[2][5] = fmaf(a2, b1.y, acc[2][5]);
        acc[2][6] = fmaf(a2, b1.z, acc[2][6]);
        acc[2][7] = fmaf(a2, b1.w, acc[2][7]);

        a0 = na0; a1 = na1; a2 = na2;
        b0 = nb0; b1 = nb1;
    }

    // Groups 1..3 store partials; group 0 sums all and writes out.
    if (g != 0) {
        float* base = sP + (g - 1) * PSZ;
        #pragma unroll
        for (int i = 0; i < 3; ++i) {
            int m = m0 + i;
            if (m < 44) {
                float* p = base + m * DIMN + c0;
                *(float4*)p       = make_float4(acc[i][0], acc[i][1], acc[i][2], acc[i][3]);
                *(float4*)(p + 4) = make_float4(acc[i][4], acc[i][5], acc[i][6], acc[i][7]);
            }
        }
    }
    __syncthreads();
    if (g == 0) {
        const int rowbase = 40 + mb;
        #pragma unroll
        for (int i = 0; i < 3; ++i) {
            int m = m0 + i;
            if (m < 44) {
                const float* p0 = sP + 0 * PSZ + m * DIMN + c0;
                const float* p1 = sP + 1 * PSZ + m * DIMN + c0;
                const float* p2 = sP + 2 * PSZ + m * DIMN + c0;
                float4 x0 = *(const float4*)p0;
                float4 y0 = *(const float4*)(p0 + 4);
                float4 x1 = *(const float4*)p1;
                float4 y1 = *(const float4*)(p1 + 4);
                float4 x2 = *(const float4*)p2;
                float4 y2 = *(const float4*)(p2 + 4);
                float* o = O + (size_t)(rowbase + m) * DIMN + c0;
                *(float4*)o = make_float4(
                    acc[i][0] + x0.x + x1.x + x2.x,
                    acc[i][1] + x0.y + x1.y + x2.y,
                    acc[i][2] + x0.z + x1.z + x2.z,
                    acc[i][3] + x0.w + x1.w + x2.w);
                *(float4*)(o + 4) = make_float4(
                    acc[i][4] + y0.x + y1.x + y2.x,
                    acc[i][5] + y0.y + y1.y + y2.y,
                    acc[i][6] + y0.z + y1.z + y2.z,
                    acc[i][7] + y0.w + y1.w + y2.w);
            }
        }
    }
}

extern "C" void kernel_launch(void* const* d_in, const int* in_sizes, int n_in,
                              void* d_out, int out_size)
{
    const float* thetas = (const float*)d_in[0];
    const int*   ri     = (const int*)d_in[1];
    const int*   rj     = (const int*)d_in[2];
    float*       out    = (float*)d_out;

    const size_t smem1 = SM_FLOATS * sizeof(float);    // 103712 B
    const size_t smem2 = GSM_FLOATS * sizeof(float);   // 129536 B
    cudaFuncSetAttribute(givens_half_kernel,
                         cudaFuncAttributeMaxDynamicSharedMemorySize, (int)smem1);
    cudaFuncSetAttribute(combine_kernel,
                         cudaFuncAttributeMaxDynamicSharedMemorySize, (int)smem2);

    givens_half_kernel<<<2 * NHEADS, TPB, smem1>>>(thetas, ri, rj);
    combine_kernel<<<2 * NHEADS, GTPB, smem2>>>(out);
}